// round 3
// baseline (speedup 1.0000x reference)
#include <cuda_runtime.h>

// decoder_fm: out[b] = 0.5*(sum_k (x@V)_k^2 - sum_j x_j^2 * s_j) + x.w + fc_b
//                      + b_users[user[b]] + b_items[item[b]] + 4.0
// x = concat(user_emb[user[b]], item_emb[item[b]])  (128 floats)
// s_j = sum_k V[j][k]^2  (precomputed per block in smem)
//
// Mapping: 16 lanes per row (2 rows per warp). Lane `sub` owns float4 chunk
// `sub` of the user half and chunk `sub` of the item half. 16 rows per
// 256-thread block -> 1024 blocks, 8192 warps: latency-hiding for the random
// 256B embedding-row gathers.

__global__ __launch_bounds__(256) void fm_kernel(
    const int* __restrict__ user, const int* __restrict__ item,
    const float* __restrict__ user_emb, const float* __restrict__ item_emb,
    const float* __restrict__ fc_w, const float* __restrict__ fc_b,
    const float* __restrict__ fm_V,
    const float* __restrict__ b_users, const float* __restrict__ b_items,
    float* __restrict__ out, int nrows)
{
    __shared__ float  sw[128];        // fc_w
    __shared__ float  ss[128];        // sum_k V[j][k]^2
    __shared__ float2 sV[5][128];     // sV[k2][j] = (V[j][2k2], V[j][2k2+1])

    const int tid = threadIdx.x;
    if (tid < 128) {
        float v[10];
        #pragma unroll
        for (int k = 0; k < 10; k++) v[k] = fm_V[tid * 10 + k];
        float s = 0.f;
        #pragma unroll
        for (int k = 0; k < 10; k++) s = fmaf(v[k], v[k], s);
        ss[tid] = s;
        sw[tid] = fc_w[tid];
        #pragma unroll
        for (int k2 = 0; k2 < 5; k2++)
            sV[k2][tid] = make_float2(v[2 * k2], v[2 * k2 + 1]);
    }
    __syncthreads();

    const int lane = tid & 31;
    const int sub  = lane & 15;   // float4-chunk within each half (0..15)
    const int rw   = lane >> 4;   // row within warp (0..1)
    const int warp = tid >> 5;    // 0..7
    const int row  = blockIdx.x * 16 + warp * 2 + rw;
    if (row >= nrows) return;

    const int u  = user[row];
    const int it = item[row];

    // Issue both gathers up front (independent -> MLP=2 per lane, 32 lines/warp)
    const float4 xu = reinterpret_cast<const float4*>(user_emb + (long long)u  * 64)[sub];
    const float4 xi = reinterpret_cast<const float4*>(item_emb + (long long)it * 64)[sub];

    float lin = 0.f, x2s = 0.f;
    float xv[10];
    #pragma unroll
    for (int k = 0; k < 10; k++) xv[k] = 0.f;

    const int j0u = sub * 4;        // j base in user half
    const int j0i = 64 + sub * 4;   // j base in item half

    #pragma unroll
    for (int h = 0; h < 2; h++) {
        const float4 xq = h ? xi : xu;
        const int    j0 = h ? j0i : j0u;

        const float4 wq = *reinterpret_cast<const float4*>(&sw[j0]);
        const float4 sq = *reinterpret_cast<const float4*>(&ss[j0]);
        const float xs[4] = {xq.x, xq.y, xq.z, xq.w};
        const float ws[4] = {wq.x, wq.y, wq.z, wq.w};
        const float s2[4] = {sq.x, sq.y, sq.z, sq.w};

        #pragma unroll
        for (int c = 0; c < 4; c++) {
            lin = fmaf(xs[c], ws[c], lin);
            x2s = fmaf(xs[c] * xs[c], s2[c], x2s);
        }
        #pragma unroll
        for (int k2 = 0; k2 < 5; k2++) {
            const float4 va = *reinterpret_cast<const float4*>(&sV[k2][j0]);      // j0, j0+1
            const float4 vb = *reinterpret_cast<const float4*>(&sV[k2][j0 + 2]);  // j0+2, j0+3
            xv[2 * k2]     = fmaf(xs[0], va.x, xv[2 * k2]);
            xv[2 * k2 + 1] = fmaf(xs[0], va.y, xv[2 * k2 + 1]);
            xv[2 * k2]     = fmaf(xs[1], va.z, xv[2 * k2]);
            xv[2 * k2 + 1] = fmaf(xs[1], va.w, xv[2 * k2 + 1]);
            xv[2 * k2]     = fmaf(xs[2], vb.x, xv[2 * k2]);
            xv[2 * k2 + 1] = fmaf(xs[2], vb.y, xv[2 * k2 + 1]);
            xv[2 * k2]     = fmaf(xs[3], vb.z, xv[2 * k2]);
            xv[2 * k2 + 1] = fmaf(xs[3], vb.w, xv[2 * k2 + 1]);
        }
    }

    // Reduce the 12 partial sums across the 16 sub-lanes of this row.
    // xor masks 1,2,4,8 never cross the 16-lane group boundary.
    const unsigned gmask = 0xFFFFu << (rw * 16);
    #pragma unroll
    for (int m = 1; m <= 8; m <<= 1) {
        lin += __shfl_xor_sync(gmask, lin, m);
        x2s += __shfl_xor_sync(gmask, x2s, m);
        #pragma unroll
        for (int k = 0; k < 10; k++)
            xv[k] += __shfl_xor_sync(gmask, xv[k], m);
    }

    if (sub == 0) {
        float inter = -x2s;
        #pragma unroll
        for (int k = 0; k < 10; k++) inter = fmaf(xv[k], xv[k], inter);
        const float r = 0.5f * inter + lin + fc_b[0]
                      + b_users[u] + b_items[it] + 4.0f;
        out[row] = r;
    }
}

extern "C" void kernel_launch(void* const* d_in, const int* in_sizes, int n_in,
                              void* d_out, int out_size)
{
    // metadata order: user, item, u_out, i_out, user_emb, item_emb,
    //                 fc_w, fc_b, fm_V, b_users, b_items
    const int*   user     = (const int*)d_in[0];
    const int*   item     = (const int*)d_in[1];
    const float* user_emb = (const float*)d_in[4];
    const float* item_emb = (const float*)d_in[5];
    const float* fc_w     = (const float*)d_in[6];
    const float* fc_b     = (const float*)d_in[7];
    const float* fm_V     = (const float*)d_in[8];
    const float* b_users  = (const float*)d_in[9];
    const float* b_items  = (const float*)d_in[10];
    float* out = (float*)d_out;

    const int nrows = in_sizes[0];
    const int grid  = (nrows + 15) / 16;   // 16 rows per 256-thread block
    fm_kernel<<<grid, 256>>>(user, item, user_emb, item_emb,
                             fc_w, fc_b, fm_V, b_users, b_items, out, nrows);
}

// round 4
// speedup vs baseline: 1.2857x; 1.2857x over previous
#include <cuda_runtime.h>

// decoder_fm: out[b] = 0.5*(sum_k (x@V)_k^2 - sum_j x_j^2*s_j) + x.w + fc_b
//                      + b_users[user[b]] + b_items[item[b]] + 4.0
// x = concat(user_emb[user[b]], item_emb[item[b]]), s_j = sum_k V[j][k]^2.
//
// R4 mapping: warp PAIRS per 8 rows. Even warp handles the user half
// (j 0..63), odd warp the item half (j 64..127) of the same 8 rows.
// Within a warp: 4 lanes per row (sub = lane&3), 8 rows (rw = lane>>2).
// Partials (lin, x2s, xv[0..9]) reduced with 2 shfl steps, combined across
// the half-pair via shared memory. 4096 warps total -> one resident wave.
// FMA stream uses packed fma.rn.f32x2.

#define PACK2(d, lo, hi)  asm("mov.b64 %0, {%1, %2};" : "=l"(d) : "f"(lo), "f"(hi))
#define UNPACK2(lo, hi, s) asm("mov.b64 {%0, %1}, %2;" : "=f"(lo), "=f"(hi) : "l"(s))
#define FMA2(d, a, b)     asm("fma.rn.f32x2 %0, %1, %2, %3;" : "=l"(d) : "l"(a), "l"(b), "l"(d))
#define ADD2(d, a, b)     asm("add.rn.f32x2 %0, %1, %2;" : "=l"(d) : "l"(a), "l"(b))

__global__ __launch_bounds__(128) void fm_kernel(
    const int* __restrict__ user, const int* __restrict__ item,
    const float* __restrict__ user_emb, const float* __restrict__ item_emb,
    const float* __restrict__ fc_w, const float* __restrict__ fc_b,
    const float* __restrict__ fm_V,
    const float* __restrict__ b_users, const float* __restrict__ b_items,
    float* __restrict__ out, int nrows)
{
    __shared__ __align__(16) float2 sws[128];      // (fc_w[j], s_j)
    __shared__ __align__(16) float2 sV[5][128];    // (V[j][2k2], V[j][2k2+1])
    __shared__ __align__(16) float  psum[16][2][12]; // [rowLocal][half][xv0..9,lin,x2s]

    const int tid = threadIdx.x;

    // ---- parameter staging (all 128 threads, one j each) ----
    {
        float v[10];
        #pragma unroll
        for (int k = 0; k < 10; k++) v[k] = fm_V[tid * 10 + k];
        float s = 0.f;
        #pragma unroll
        for (int k = 0; k < 10; k++) s = fmaf(v[k], v[k], s);
        sws[tid] = make_float2(fc_w[tid], s);
        #pragma unroll
        for (int k2 = 0; k2 < 5; k2++)
            sV[k2][tid] = make_float2(v[2 * k2], v[2 * k2 + 1]);
    }
    __syncthreads();

    const int lane = tid & 31;
    const int warp = tid >> 5;        // 0..3
    const int pair = warp >> 1;       // 0..1
    const int half = warp & 1;        // 0 = user half, 1 = item half
    const int sub  = lane & 3;        // element slice within a row
    const int rw   = lane >> 2;       // row within warp (0..7)
    const int rowL = pair * 8 + rw;   // row within block (0..15)
    const int row  = blockIdx.x * 16 + rowL;

    if (row < nrows) {
        const int idx = half ? item[row] : user[row];
        const float* tab = half ? item_emb : user_emb;
        const float4* rp = reinterpret_cast<const float4*>(tab + (long long)idx * 64);

        // gather this warp's half-row: 4 float4 per lane, fully coalesced
        float4 xq[4];
        #pragma unroll
        for (int c = 0; c < 4; c++) xq[c] = rp[c * 4 + sub];

        unsigned long long acc_ls = 0ull;   // (lin, x2s)
        unsigned long long acc2[5];
        #pragma unroll
        for (int k2 = 0; k2 < 5; k2++) acc2[k2] = 0ull;

        #pragma unroll
        for (int c = 0; c < 4; c++) {
            const int j0 = half * 64 + (c * 4 + sub) * 4;
            const float xs[4] = {xq[c].x, xq[c].y, xq[c].z, xq[c].w};

            const ulonglong2 wsA = *reinterpret_cast<const ulonglong2*>(&sws[j0]);     // j0, j0+1
            const ulonglong2 wsB = *reinterpret_cast<const ulonglong2*>(&sws[j0 + 2]); // j0+2, j0+3
            const unsigned long long wsp[4] = {wsA.x, wsA.y, wsB.x, wsB.y};

            ulonglong2 vA[5], vB[5];
            #pragma unroll
            for (int k2 = 0; k2 < 5; k2++) {
                vA[k2] = *reinterpret_cast<const ulonglong2*>(&sV[k2][j0]);
                vB[k2] = *reinterpret_cast<const ulonglong2*>(&sV[k2][j0 + 2]);
            }

            #pragma unroll
            for (int jj = 0; jj < 4; jj++) {
                const float x = xs[jj];
                unsigned long long xp, xsq;
                PACK2(xp,  x, x);
                PACK2(xsq, x, x * x);
                FMA2(acc_ls, xsq, wsp[jj]);          // lin += x*w ; x2s += x^2*s
                #pragma unroll
                for (int k2 = 0; k2 < 5; k2++) {
                    const unsigned long long vj =
                        (jj == 0) ? vA[k2].x : (jj == 1) ? vA[k2].y
                                 : (jj == 2) ? vB[k2].x : vB[k2].y;
                    FMA2(acc2[k2], xp, vj);          // xv[2k2], xv[2k2+1]
                }
            }
        }

        // reduce across the 4 sub-lanes of this row (2 butterfly steps)
        #pragma unroll
        for (int m = 1; m <= 2; m <<= 1) {
            unsigned long long t;
            t = __shfl_xor_sync(0xFFFFFFFFu, acc_ls, m); ADD2(acc_ls, acc_ls, t);
            #pragma unroll
            for (int k2 = 0; k2 < 5; k2++) {
                t = __shfl_xor_sync(0xFFFFFFFFu, acc2[k2], m); ADD2(acc2[k2], acc2[k2], t);
            }
        }

        if (sub == 0) {
            float tmp[12];
            #pragma unroll
            for (int k2 = 0; k2 < 5; k2++) UNPACK2(tmp[2 * k2], tmp[2 * k2 + 1], acc2[k2]);
            UNPACK2(tmp[10], tmp[11], acc_ls);       // lin, x2s
            float4* dst = reinterpret_cast<float4*>(&psum[rowL][half][0]);
            dst[0] = make_float4(tmp[0], tmp[1], tmp[2],  tmp[3]);
            dst[1] = make_float4(tmp[4], tmp[5], tmp[6],  tmp[7]);
            dst[2] = make_float4(tmp[8], tmp[9], tmp[10], tmp[11]);
        }
    }
    __syncthreads();

    // ---- combine halves: one thread per row ----
    if (tid < 16) {
        const int grow = blockIdx.x * 16 + tid;
        if (grow < nrows) {
            const float4* pa = reinterpret_cast<const float4*>(&psum[tid][0][0]);
            const float4* pb = reinterpret_cast<const float4*>(&psum[tid][1][0]);
            float a[12], b[12];
            #pragma unroll
            for (int q = 0; q < 3; q++) {
                const float4 fa = pa[q], fb = pb[q];
                a[4*q+0]=fa.x; a[4*q+1]=fa.y; a[4*q+2]=fa.z; a[4*q+3]=fa.w;
                b[4*q+0]=fb.x; b[4*q+1]=fb.y; b[4*q+2]=fb.z; b[4*q+3]=fb.w;
            }
            float inter = -(a[11] + b[11]);          // -x2s
            #pragma unroll
            for (int k = 0; k < 10; k++) {
                const float xv = a[k] + b[k];
                inter = fmaf(xv, xv, inter);
            }
            const float lin = a[10] + b[10];
            const int u  = user[grow];
            const int it = item[grow];
            out[grow] = 0.5f * inter + lin + fc_b[0]
                      + b_users[u] + b_items[it] + 4.0f;
        }
    }
}

extern "C" void kernel_launch(void* const* d_in, const int* in_sizes, int n_in,
                              void* d_out, int out_size)
{
    // metadata order: user, item, u_out, i_out, user_emb, item_emb,
    //                 fc_w, fc_b, fm_V, b_users, b_items
    const int*   user     = (const int*)d_in[0];
    const int*   item     = (const int*)d_in[1];
    const float* user_emb = (const float*)d_in[4];
    const float* item_emb = (const float*)d_in[5];
    const float* fc_w     = (const float*)d_in[6];
    const float* fc_b     = (const float*)d_in[7];
    const float* fm_V     = (const float*)d_in[8];
    const float* b_users  = (const float*)d_in[9];
    const float* b_items  = (const float*)d_in[10];
    float* out = (float*)d_out;

    const int nrows = in_sizes[0];
    const int grid  = (nrows + 15) / 16;   // 16 rows per 128-thread block
    fm_kernel<<<grid, 128>>>(user, item, user_emb, item_emb,
                             fc_w, fc_b, fm_V, b_users, b_items, out, nrows);
}